// round 11
// baseline (speedup 1.0000x reference)
#include <cuda_runtime.h>
#include <math.h>

#define NB    64
#define NC    256
#define HW    4096            // 64*64
#define NPLANES 16384
#define HIDD  16
#define NCOND 32
#define RHID  64
#define ZGRID 2960            // 148 SMs x 20
#define CHUNK 2               // droplist entries per block iter

// ---- scratch (no allocations allowed; zero-initialized at module load) ----
__device__ float g_semantic[NPLANES];
__device__ int   g_droplist[NPLANES];
__device__ int   g_ndrop;
__device__ int   g_batch_done[NB];
__device__ int   g_zero_done;

// ---------------------------------------------------------------------------
__device__ __forceinline__ float warp_sum(float v) {
#pragma unroll
    for (int o = 16; o > 0; o >>= 1)
        v += __shfl_down_sync(0xffffffffu, v, o);
    return v;
}

// ---------------------------------------------------------------------------
// Select for batch b, executed inline by one whole block (256 threads).
// Warp-parallel dot products (coalesced); g_semantic read via __ldcg after
// fence+atomic ordering.
// ---------------------------------------------------------------------------
__device__ __noinline__ void do_select(
    int b, int t,
    const float* __restrict__ base_cr,
    const float* __restrict__ embed,  const float* __restrict__ snr_w1,
    const float* __restrict__ snr_b1, const float* __restrict__ snr_w2,
    const float* __restrict__ snr_b2, const float* __restrict__ sem_w,
    const float* __restrict__ cond_w, const float* __restrict__ out_w,
    const float* __restrict__ r_w1,   const float* __restrict__ r_b1,
    const float* __restrict__ r_w2,   const float* __restrict__ r_b2,
    const float* __restrict__ r_w3,   const float* __restrict__ r_b3,
    const int*   __restrict__ channel_idx, const int* __restrict__ snr_db,
    float* __restrict__ out_cr)
{
    const int warp = t >> 5;
    const int lane = t & 31;

    __shared__ float sem[NC];
    __shared__ float cond[NCOND];
    __shared__ float fused[HIDD];
    __shared__ float w[NC];
    __shared__ float r1[RHID];
    __shared__ float r2[RHID];
    __shared__ int   k_sh;

    sem[t] = __ldcg(&g_semantic[b * NC + t]);

    if (t < HIDD) {
        cond[t] = embed[channel_idx[0] * 16 + t];
    } else if (t < 2 * HIDD) {
        const int i = t - HIDD;
        const float snr_norm = (float)snr_db[0] / 28.0f;
        float acc = snr_b2[i];
#pragma unroll
        for (int j = 0; j < 16; ++j) {
            float hj = fmaxf(snr_norm * snr_w1[j] + snr_b1[j], 0.0f);
            acc += hj * snr_w2[i * 16 + j];
        }
        cond[16 + i] = fmaxf(acc, 0.0f);
    }
    __syncthreads();

    // ---- phase A: fused[16] (2 per warp) + r1[64] (8 per warp) ----
#pragma unroll
    for (int q = 0; q < 2; ++q) {
        const int o = warp * 2 + q;
        float acc = 0.0f;
#pragma unroll
        for (int j = lane; j < NC; j += 32) acc += sem[j] * sem_w[o * NC + j];
        acc += cond[lane] * cond_w[o * NCOND + lane];
        acc = warp_sum(acc);
        if (lane == 0) fused[o] = fmaxf(acc, 0.0f);
    }
#pragma unroll
    for (int q = 0; q < 8; ++q) {
        const int o = warp * 8 + q;
        const float* __restrict__ wr = r_w1 + o * (NC + NCOND);
        float acc = 0.0f;
#pragma unroll
        for (int j = lane; j < NC; j += 32) acc += sem[j] * wr[j];
        acc += cond[lane] * wr[NC + lane];
        acc = warp_sum(acc);
        if (lane == 0) r1[o] = fmaxf(acc + r_b1[o], 0.0f);
    }
    __syncthreads();

    // ---- phase B: weights[256] (1 per thread) + r2[64] ----
    {
        const float4* __restrict__ ow =
            reinterpret_cast<const float4*>(out_w + t * HIDD);
        float acc = 0.0f;
#pragma unroll
        for (int q = 0; q < 4; ++q) {
            float4 v = ow[q];
            acc += v.x * fused[q * 4 + 0] + v.y * fused[q * 4 + 1]
                 + v.z * fused[q * 4 + 2] + v.w * fused[q * 4 + 3];
        }
        w[t] = 1.0f / (1.0f + expf(-acc));
    }
#pragma unroll
    for (int q = 0; q < 8; ++q) {
        const int o = warp * 8 + q;
        float acc = r1[lane]      * r_w2[o * RHID + lane]
                  + r1[lane + 32] * r_w2[o * RHID + lane + 32];
        acc = warp_sum(acc);
        if (lane == 0) r2[o] = fmaxf(acc + r_b2[o], 0.0f);
    }
    __syncthreads();

    // ---- phase C: r3 scalar + cr + k (warp 0) ----
    if (warp == 0) {
        float acc = r2[lane]      * r_w3[lane]
                  + r2[lane + 32] * r_w3[lane + 32];
        acc = warp_sum(acc);
        if (lane == 0) {
            acc += r_b3[0];
            float raw = 1.0f / (1.0f + expf(-acc));
            float dyn = 0.3f + 0.7f * raw;
            float cr  = 0.3f * base_cr[0] + 0.7f * dyn;
            cr = fminf(fmaxf(cr, 0.3f), 1.0f);
            out_cr[b] = cr;
            float crs = fminf(fmaxf(cr, 0.001f), 1.0f);
            int kk = (int)rintf(crs * 256.0f);   // round-half-even == jnp.round
            kk = min(max(kk, 1), 256);
            k_sh = kk;
        }
    }
    __syncthreads();

    // ---- stable descending rank; dropped channels -> compact list ----
    const float wc = w[t];
    int rank = 0;
    for (int j = 0; j < NC; ++j) {
        float wj = w[j];
        rank += (wj > wc) || (wj == wc && j < t);
    }
    if (rank >= k_sh) {
        int i = atomicAdd(&g_ndrop, 1);
        g_droplist[i] = b * NC + t;
    }
}

// ---------------------------------------------------------------------------
// Pass 1: y = x (streaming copy) + per-plane sum; the last-finishing block of
// each batch runs that batch's select inline. 16384 blocks x 256 threads.
// ---------------------------------------------------------------------------
__global__ void __launch_bounds__(256, 8) copy_reduce_kernel(
    const float* __restrict__ x, float* __restrict__ y,
    const float* __restrict__ base_cr,
    const float* __restrict__ embed,  const float* __restrict__ snr_w1,
    const float* __restrict__ snr_b1, const float* __restrict__ snr_w2,
    const float* __restrict__ snr_b2, const float* __restrict__ sem_w,
    const float* __restrict__ cond_w, const float* __restrict__ out_w,
    const float* __restrict__ r_w1,   const float* __restrict__ r_b1,
    const float* __restrict__ r_w2,   const float* __restrict__ r_b2,
    const float* __restrict__ r_w3,   const float* __restrict__ r_b3,
    const int*   __restrict__ channel_idx, const int* __restrict__ snr_db,
    float* __restrict__ out_cr)
{
    const int bc = blockIdx.x;
    const int b  = bc >> 8;
    const int t  = threadIdx.x;

    const float4* __restrict__ xi =
        reinterpret_cast<const float4*>(x + (size_t)bc * HW);
    float4* __restrict__ yo =
        reinterpret_cast<float4*>(y + (size_t)bc * HW);

    float4 v[4];
#pragma unroll
    for (int j = 0; j < 4; ++j) v[j] = __ldcs(&xi[t + 256 * j]);

    float s = 0.0f;
#pragma unroll
    for (int j = 0; j < 4; ++j) {
        __stcs(&yo[t + 256 * j], v[j]);
        s += (v[j].x + v[j].y) + (v[j].z + v[j].w);
    }
#pragma unroll
    for (int o = 16; o > 0; o >>= 1)
        s += __shfl_down_sync(0xffffffffu, s, o);

    __shared__ float ws[8];
    __shared__ int   last;
    if ((t & 31) == 0) ws[t >> 5] = s;
    __syncthreads();
    if (t == 0) {
        float tot = ((ws[0] + ws[1]) + (ws[2] + ws[3]))
                  + ((ws[4] + ws[5]) + (ws[6] + ws[7]));
        g_semantic[bc] = tot * (1.0f / 4096.0f);
        __threadfence();                            // release g_semantic
        int old = atomicAdd(&g_batch_done[b], 1);
        last = (old == NC - 1);
        if (last) __threadfence();                  // acquire others' stores
    }
    __syncthreads();
    if (last) {
        do_select(b, t, base_cr, embed, snr_w1, snr_b1, snr_w2, snr_b2,
                  sem_w, cond_w, out_w, r_w1, r_b1, r_w2, r_b2, r_w3, r_b3,
                  channel_idx, snr_db, out_cr);
    }
}

// ---------------------------------------------------------------------------
// Pass 2: zero dropped planes. 2960 blocks x 256 threads, CHUNK=2 planes per
// block iter. The LAST finishing block resets all inter-launch counters so no
// separate init kernel is needed on the next graph replay (every block has
// already read g_ndrop/droplist by then; stream order protects the next copy).
// ---------------------------------------------------------------------------
__global__ void __launch_bounds__(256) zero_kernel(float* __restrict__ y) {
    const int n = g_ndrop;
    const int t = threadIdx.x;
    __shared__ int idxs[CHUNK];
    const float4 z = make_float4(0.0f, 0.0f, 0.0f, 0.0f);

    for (int base = blockIdx.x * CHUNK; base < n; base += ZGRID * CHUNK) {
        const int m = min(CHUNK, n - base);
        if (t < m) idxs[t] = g_droplist[base + t];
        __syncthreads();
        for (int i = 0; i < m; ++i) {
            float4* __restrict__ yo =
                reinterpret_cast<float4*>(y + (size_t)idxs[i] * HW);
#pragma unroll
            for (int j = 0; j < 4; ++j)
                __stcs(&yo[t + 256 * j], z);
        }
        __syncthreads();
    }

    // ---- counter reset by the last block to finish ----
    if (t == 0) {
        __threadfence();
        int old = atomicAdd(&g_zero_done, 1);
        if (old == ZGRID - 1) {
            g_zero_done = 0;
            g_ndrop     = 0;
#pragma unroll
            for (int i = 0; i < NB; ++i) g_batch_done[i] = 0;
            __threadfence();
        }
    }
}

// ---------------------------------------------------------------------------
extern "C" void kernel_launch(void* const* d_in, const int* in_sizes, int n_in,
                              void* d_out, int out_size) {
    const float* x       = (const float*)d_in[0];
    const float* base_cr = (const float*)d_in[1];
    const float* embed   = (const float*)d_in[2];
    const float* snr_w1  = (const float*)d_in[3];
    const float* snr_b1  = (const float*)d_in[4];
    const float* snr_w2  = (const float*)d_in[5];
    const float* snr_b2  = (const float*)d_in[6];
    const float* sem_w   = (const float*)d_in[7];
    const float* cond_w  = (const float*)d_in[8];
    const float* out_w   = (const float*)d_in[9];
    const float* r_w1    = (const float*)d_in[10];
    const float* r_b1    = (const float*)d_in[11];
    const float* r_w2    = (const float*)d_in[12];
    const float* r_b2    = (const float*)d_in[13];
    const float* r_w3    = (const float*)d_in[14];
    const float* r_b3    = (const float*)d_in[15];
    const int*   ch_idx  = (const int*)d_in[16];
    const int*   snr_db  = (const int*)d_in[17];

    float* y      = (float*)d_out;
    float* out_cr = y + (size_t)NPLANES * HW;   // cr_values appended after y

    copy_reduce_kernel<<<NPLANES, 256>>>(
        x, y, base_cr, embed, snr_w1, snr_b1, snr_w2, snr_b2, sem_w, cond_w,
        out_w, r_w1, r_b1, r_w2, r_b2, r_w3, r_b3, ch_idx, snr_db, out_cr);
    zero_kernel<<<ZGRID, 256>>>(y);
}

// round 12
// speedup vs baseline: 1.0178x; 1.0178x over previous
#include <cuda_runtime.h>
#include <math.h>

#define NB    64
#define NC    256
#define HW    4096            // 64*64
#define NPLANES 16384
#define HIDD  16
#define NCOND 32
#define RHID  64
#define ZGRID 296             // 148 SMs x 2
#define CHUNKZ 16             // droplist entries per block iter

// ---- scratch (no allocations allowed) ----
__device__ float g_semantic[NPLANES];
__device__ int   g_droplist[NPLANES];
__device__ int   g_ndrop;

// ---------------------------------------------------------------------------
// Pass 1: y = x (streaming copy) + per-plane sum. 16384 blocks x 256 threads.
// All 4 LDG.128 issued before any STG.128. Block 0 resets g_ndrop (consumed
// only after this kernel completes).
// ---------------------------------------------------------------------------
__global__ void __launch_bounds__(256) copy_reduce_kernel(
    const float* __restrict__ x, float* __restrict__ y)
{
    const int bc = blockIdx.x;
    const int t  = threadIdx.x;
    if (bc == 0 && t == 0) g_ndrop = 0;

    const float4* __restrict__ xi =
        reinterpret_cast<const float4*>(x + (size_t)bc * HW);
    float4* __restrict__ yo =
        reinterpret_cast<float4*>(y + (size_t)bc * HW);

    float4 v[4];
#pragma unroll
    for (int j = 0; j < 4; ++j) v[j] = __ldcs(&xi[t + 256 * j]);

    float s = 0.0f;
#pragma unroll
    for (int j = 0; j < 4; ++j) {
        __stcs(&yo[t + 256 * j], v[j]);
        s += (v[j].x + v[j].y) + (v[j].z + v[j].w);
    }
#pragma unroll
    for (int o = 16; o > 0; o >>= 1)
        s += __shfl_down_sync(0xffffffffu, s, o);

    __shared__ float ws[8];
    if ((t & 31) == 0) ws[t >> 5] = s;
    __syncthreads();
    if (t == 0) {
        float tot = ((ws[0] + ws[1]) + (ws[2] + ws[3]))
                  + ((ws[4] + ws[5]) + (ws[6] + ws[7]));
        g_semantic[bc] = tot * (1.0f / 4096.0f);
    }
}

// ---------------------------------------------------------------------------
__device__ __forceinline__ float warp_sum(float v) {
#pragma unroll
    for (int o = 16; o > 0; o >>= 1)
        v += __shfl_down_sync(0xffffffffu, v, o);
    return v;
}

// ---------------------------------------------------------------------------
// Pass 2: per-batch tiny MLPs + top-k mask + dropped-plane compaction.
// 64 blocks x 256 threads. Warp-parallel dot products (coalesced).
// ---------------------------------------------------------------------------
__global__ void __launch_bounds__(256) select_kernel(
    const float* __restrict__ base_cr,
    const float* __restrict__ embed,     // [3,16]
    const float* __restrict__ snr_w1,    // [16,1]
    const float* __restrict__ snr_b1,    // [16]
    const float* __restrict__ snr_w2,    // [16,16]
    const float* __restrict__ snr_b2,    // [16]
    const float* __restrict__ sem_w,     // [16,256]
    const float* __restrict__ cond_w,    // [16,32]
    const float* __restrict__ out_w,     // [256,16]
    const float* __restrict__ r_w1,      // [64,288]
    const float* __restrict__ r_b1,      // [64]
    const float* __restrict__ r_w2,      // [64,64]
    const float* __restrict__ r_b2,      // [64]
    const float* __restrict__ r_w3,      // [1,64]
    const float* __restrict__ r_b3,      // [1]
    const int*   __restrict__ channel_idx,
    const int*   __restrict__ snr_db,
    float* __restrict__ out_cr)
{
    const int b    = blockIdx.x;
    const int t    = threadIdx.x;
    const int warp = t >> 5;
    const int lane = t & 31;

    __shared__ float sem[NC];
    __shared__ float cond[NCOND];
    __shared__ float fused[HIDD];
    __shared__ float w[NC];
    __shared__ float r1[RHID];
    __shared__ float r2[RHID];
    __shared__ int   k_sh;

    sem[t] = g_semantic[b * NC + t];

    if (t < HIDD) {
        cond[t] = embed[channel_idx[0] * 16 + t];
    } else if (t < 2 * HIDD) {
        const int i = t - HIDD;
        const float snr_norm = (float)snr_db[0] / 28.0f;
        float acc = snr_b2[i];
#pragma unroll
        for (int j = 0; j < 16; ++j) {
            float hj = fmaxf(snr_norm * snr_w1[j] + snr_b1[j], 0.0f);
            acc += hj * snr_w2[i * 16 + j];
        }
        cond[16 + i] = fmaxf(acc, 0.0f);
    }
    __syncthreads();

    // ---- phase A: fused[16] (2 per warp) + r1[64] (8 per warp) ----
#pragma unroll
    for (int q = 0; q < 2; ++q) {
        const int o = warp * 2 + q;
        float acc = 0.0f;
#pragma unroll
        for (int j = lane; j < NC; j += 32) acc += sem[j] * sem_w[o * NC + j];
        acc += cond[lane] * cond_w[o * NCOND + lane];
        acc = warp_sum(acc);
        if (lane == 0) fused[o] = fmaxf(acc, 0.0f);
    }
#pragma unroll
    for (int q = 0; q < 8; ++q) {
        const int o = warp * 8 + q;
        const float* __restrict__ wr = r_w1 + o * (NC + NCOND);
        float acc = 0.0f;
#pragma unroll
        for (int j = lane; j < NC; j += 32) acc += sem[j] * wr[j];
        acc += cond[lane] * wr[NC + lane];
        acc = warp_sum(acc);
        if (lane == 0) r1[o] = fmaxf(acc + r_b1[o], 0.0f);
    }
    __syncthreads();

    // ---- phase B: weights[256] (1 per thread) + r2[64] ----
    {
        const float4* __restrict__ ow =
            reinterpret_cast<const float4*>(out_w + t * HIDD);
        float acc = 0.0f;
#pragma unroll
        for (int q = 0; q < 4; ++q) {
            float4 v = ow[q];
            acc += v.x * fused[q * 4 + 0] + v.y * fused[q * 4 + 1]
                 + v.z * fused[q * 4 + 2] + v.w * fused[q * 4 + 3];
        }
        w[t] = 1.0f / (1.0f + expf(-acc));
    }
#pragma unroll
    for (int q = 0; q < 8; ++q) {
        const int o = warp * 8 + q;
        float acc = r1[lane]      * r_w2[o * RHID + lane]
                  + r1[lane + 32] * r_w2[o * RHID + lane + 32];
        acc = warp_sum(acc);
        if (lane == 0) r2[o] = fmaxf(acc + r_b2[o], 0.0f);
    }
    __syncthreads();

    // ---- phase C: r3 scalar + cr + k (warp 0) ----
    if (warp == 0) {
        float acc = r2[lane]      * r_w3[lane]
                  + r2[lane + 32] * r_w3[lane + 32];
        acc = warp_sum(acc);
        if (lane == 0) {
            acc += r_b3[0];
            float raw = 1.0f / (1.0f + expf(-acc));
            float dyn = 0.3f + 0.7f * raw;
            float cr  = 0.3f * base_cr[0] + 0.7f * dyn;
            cr = fminf(fmaxf(cr, 0.3f), 1.0f);
            out_cr[b] = cr;
            float crs = fminf(fmaxf(cr, 0.001f), 1.0f);
            int kk = (int)rintf(crs * 256.0f);   // round-half-even == jnp.round
            kk = min(max(kk, 1), 256);
            k_sh = kk;
        }
    }
    __syncthreads();

    // ---- stable descending rank; dropped channels -> compact list ----
    const float wc = w[t];
    int rank = 0;
    for (int j = 0; j < NC; ++j) {
        float wj = w[j];
        rank += (wj > wc) || (wj == wc && j < t);
    }
    if (rank >= k_sh) {
        int i = atomicAdd(&g_ndrop, 1);
        g_droplist[i] = b * NC + t;
    }
}

// ---------------------------------------------------------------------------
// Pass 3: zero dropped planes with BULK async stores (smem -> gmem), one
// 16 KB cp.async.bulk per plane instead of ~1K STG.128s. 296 blocks.
// ---------------------------------------------------------------------------
__global__ void __launch_bounds__(256) zero_kernel(float* __restrict__ y) {
    const int n = g_ndrop;
    const int t = threadIdx.x;
    __shared__ alignas(128) float zbuf[HW];     // 16 KB of zeros
    __shared__ int idxs[CHUNKZ];

    float4* zb = reinterpret_cast<float4*>(zbuf);
#pragma unroll
    for (int j = 0; j < 4; ++j)
        zb[t + 256 * j] = make_float4(0.0f, 0.0f, 0.0f, 0.0f);
    __syncthreads();
    asm volatile("fence.proxy.async.shared::cta;" ::: "memory");

    const unsigned int saddr =
        (unsigned int)__cvta_generic_to_shared(zbuf);
    const unsigned int nbytes = HW * 4;

    for (int base = blockIdx.x * CHUNKZ; base < n; base += ZGRID * CHUNKZ) {
        const int m = min(CHUNKZ, n - base);
        if (t < m) idxs[t] = g_droplist[base + t];
        __syncthreads();
        if (t == 0) {
            for (int i = 0; i < m; ++i) {
                float* gdst = y + (size_t)idxs[i] * HW;
                asm volatile(
                    "cp.async.bulk.global.shared::cta.bulk_group [%0], [%1], %2;"
                    :: "l"(gdst), "r"(saddr), "r"(nbytes) : "memory");
            }
        }
        __syncthreads();
    }

    if (t == 0) {
        asm volatile("cp.async.bulk.commit_group;" ::: "memory");
        asm volatile("cp.async.bulk.wait_group 0;" ::: "memory");
    }
    __syncthreads();
}

// ---------------------------------------------------------------------------
extern "C" void kernel_launch(void* const* d_in, const int* in_sizes, int n_in,
                              void* d_out, int out_size) {
    const float* x       = (const float*)d_in[0];
    const float* base_cr = (const float*)d_in[1];
    const float* embed   = (const float*)d_in[2];
    const float* snr_w1  = (const float*)d_in[3];
    const float* snr_b1  = (const float*)d_in[4];
    const float* snr_w2  = (const float*)d_in[5];
    const float* snr_b2  = (const float*)d_in[6];
    const float* sem_w   = (const float*)d_in[7];
    const float* cond_w  = (const float*)d_in[8];
    const float* out_w   = (const float*)d_in[9];
    const float* r_w1    = (const float*)d_in[10];
    const float* r_b1    = (const float*)d_in[11];
    const float* r_w2    = (const float*)d_in[12];
    const float* r_b2    = (const float*)d_in[13];
    const float* r_w3    = (const float*)d_in[14];
    const float* r_b3    = (const float*)d_in[15];
    const int*   ch_idx  = (const int*)d_in[16];
    const int*   snr_db  = (const int*)d_in[17];

    float* y      = (float*)d_out;
    float* out_cr = y + (size_t)NPLANES * HW;   // cr_values appended after y

    copy_reduce_kernel<<<NPLANES, 256>>>(x, y);
    select_kernel<<<NB, 256>>>(base_cr, embed, snr_w1, snr_b1, snr_w2, snr_b2,
                               sem_w, cond_w, out_w,
                               r_w1, r_b1, r_w2, r_b2, r_w3, r_b3,
                               ch_idx, snr_db, out_cr);
    zero_kernel<<<ZGRID, 256>>>(y);
}

// round 13
// speedup vs baseline: 1.0187x; 1.0008x over previous
#include <cuda_runtime.h>
#include <math.h>

#define NB    64
#define NC    256
#define HW    4096            // 64*64
#define NPLANES 16384
#define HIDD  16
#define NCOND 32
#define RHID  64
#define ZGRID 1184            // 148 SMs x 8

// ---- scratch (no allocations allowed) ----
__device__ float g_semantic[NPLANES];
__device__ int   g_droplist[NPLANES];
__device__ int   g_ndrop;

// ---------------------------------------------------------------------------
// Pass 1: y = x (streaming copy) + per-plane sum. 16384 blocks x 256 threads.
// All 4 LDG.128 issued before any STG.128. Block 0 resets g_ndrop (consumed
// only after this kernel completes).
// ---------------------------------------------------------------------------
__global__ void __launch_bounds__(256) copy_reduce_kernel(
    const float* __restrict__ x, float* __restrict__ y)
{
    const int bc = blockIdx.x;
    const int t  = threadIdx.x;
    if (bc == 0 && t == 0) g_ndrop = 0;

    const float4* __restrict__ xi =
        reinterpret_cast<const float4*>(x + (size_t)bc * HW);
    float4* __restrict__ yo =
        reinterpret_cast<float4*>(y + (size_t)bc * HW);

    float4 v[4];
#pragma unroll
    for (int j = 0; j < 4; ++j) v[j] = __ldcs(&xi[t + 256 * j]);

    float s = 0.0f;
#pragma unroll
    for (int j = 0; j < 4; ++j) {
        __stcs(&yo[t + 256 * j], v[j]);
        s += (v[j].x + v[j].y) + (v[j].z + v[j].w);
    }
#pragma unroll
    for (int o = 16; o > 0; o >>= 1)
        s += __shfl_down_sync(0xffffffffu, s, o);

    __shared__ float ws[8];
    if ((t & 31) == 0) ws[t >> 5] = s;
    __syncthreads();
    if (t == 0) {
        float tot = ((ws[0] + ws[1]) + (ws[2] + ws[3]))
                  + ((ws[4] + ws[5]) + (ws[6] + ws[7]));
        g_semantic[bc] = tot * (1.0f / 4096.0f);
    }
}

// ---------------------------------------------------------------------------
__device__ __forceinline__ float warp_sum(float v) {
#pragma unroll
    for (int o = 16; o > 0; o >>= 1)
        v += __shfl_down_sync(0xffffffffu, v, o);
    return v;
}

// ---------------------------------------------------------------------------
// Pass 2: per-batch tiny MLPs + top-k mask + dropped-plane compaction.
// 64 blocks x 256 threads. Warp-parallel dot products (coalesced).
// ---------------------------------------------------------------------------
__global__ void __launch_bounds__(256) select_kernel(
    const float* __restrict__ base_cr,
    const float* __restrict__ embed,     // [3,16]
    const float* __restrict__ snr_w1,    // [16,1]
    const float* __restrict__ snr_b1,    // [16]
    const float* __restrict__ snr_w2,    // [16,16]
    const float* __restrict__ snr_b2,    // [16]
    const float* __restrict__ sem_w,     // [16,256]
    const float* __restrict__ cond_w,    // [16,32]
    const float* __restrict__ out_w,     // [256,16]
    const float* __restrict__ r_w1,      // [64,288]
    const float* __restrict__ r_b1,      // [64]
    const float* __restrict__ r_w2,      // [64,64]
    const float* __restrict__ r_b2,      // [64]
    const float* __restrict__ r_w3,      // [1,64]
    const float* __restrict__ r_b3,      // [1]
    const int*   __restrict__ channel_idx,
    const int*   __restrict__ snr_db,
    float* __restrict__ out_cr)
{
    const int b    = blockIdx.x;
    const int t    = threadIdx.x;
    const int warp = t >> 5;
    const int lane = t & 31;

    __shared__ float sem[NC];
    __shared__ float cond[NCOND];
    __shared__ float fused[HIDD];
    __shared__ float w[NC];
    __shared__ float r1[RHID];
    __shared__ float r2[RHID];
    __shared__ int   k_sh;

    sem[t] = g_semantic[b * NC + t];

    if (t < HIDD) {
        cond[t] = embed[channel_idx[0] * 16 + t];
    } else if (t < 2 * HIDD) {
        const int i = t - HIDD;
        const float snr_norm = (float)snr_db[0] / 28.0f;
        float acc = snr_b2[i];
#pragma unroll
        for (int j = 0; j < 16; ++j) {
            float hj = fmaxf(snr_norm * snr_w1[j] + snr_b1[j], 0.0f);
            acc += hj * snr_w2[i * 16 + j];
        }
        cond[16 + i] = fmaxf(acc, 0.0f);
    }
    __syncthreads();

    // ---- phase A: fused[16] (2 per warp) + r1[64] (8 per warp) ----
#pragma unroll
    for (int q = 0; q < 2; ++q) {
        const int o = warp * 2 + q;
        float acc = 0.0f;
#pragma unroll
        for (int j = lane; j < NC; j += 32) acc += sem[j] * sem_w[o * NC + j];
        acc += cond[lane] * cond_w[o * NCOND + lane];
        acc = warp_sum(acc);
        if (lane == 0) fused[o] = fmaxf(acc, 0.0f);
    }
#pragma unroll
    for (int q = 0; q < 8; ++q) {
        const int o = warp * 8 + q;
        const float* __restrict__ wr = r_w1 + o * (NC + NCOND);
        float acc = 0.0f;
#pragma unroll
        for (int j = lane; j < NC; j += 32) acc += sem[j] * wr[j];
        acc += cond[lane] * wr[NC + lane];
        acc = warp_sum(acc);
        if (lane == 0) r1[o] = fmaxf(acc + r_b1[o], 0.0f);
    }
    __syncthreads();

    // ---- phase B: weights[256] (1 per thread) + r2[64] ----
    {
        const float4* __restrict__ ow =
            reinterpret_cast<const float4*>(out_w + t * HIDD);
        float acc = 0.0f;
#pragma unroll
        for (int q = 0; q < 4; ++q) {
            float4 v = ow[q];
            acc += v.x * fused[q * 4 + 0] + v.y * fused[q * 4 + 1]
                 + v.z * fused[q * 4 + 2] + v.w * fused[q * 4 + 3];
        }
        w[t] = 1.0f / (1.0f + expf(-acc));
    }
#pragma unroll
    for (int q = 0; q < 8; ++q) {
        const int o = warp * 8 + q;
        float acc = r1[lane]      * r_w2[o * RHID + lane]
                  + r1[lane + 32] * r_w2[o * RHID + lane + 32];
        acc = warp_sum(acc);
        if (lane == 0) r2[o] = fmaxf(acc + r_b2[o], 0.0f);
    }
    __syncthreads();

    // ---- phase C: r3 scalar + cr + k (warp 0) ----
    if (warp == 0) {
        float acc = r2[lane]      * r_w3[lane]
                  + r2[lane + 32] * r_w3[lane + 32];
        acc = warp_sum(acc);
        if (lane == 0) {
            acc += r_b3[0];
            float raw = 1.0f / (1.0f + expf(-acc));
            float dyn = 0.3f + 0.7f * raw;
            float cr  = 0.3f * base_cr[0] + 0.7f * dyn;
            cr = fminf(fmaxf(cr, 0.3f), 1.0f);
            out_cr[b] = cr;
            float crs = fminf(fmaxf(cr, 0.001f), 1.0f);
            int kk = (int)rintf(crs * 256.0f);   // round-half-even == jnp.round
            kk = min(max(kk, 1), 256);
            k_sh = kk;
        }
    }
    __syncthreads();

    // ---- stable descending rank; dropped channels -> compact list ----
    const float wc = w[t];
    int rank = 0;
    for (int j = 0; j < NC; ++j) {
        float wj = w[j];
        rank += (wj > wc) || (wj == wc && j < t);
    }
    if (rank >= k_sh) {
        int i = atomicAdd(&g_ndrop, 1);
        g_droplist[i] = b * NC + t;
    }
}

// ---------------------------------------------------------------------------
// Pass 3: zero dropped planes with BULK async stores. Every THREAD issues its
// own 16 KB cp.async.bulk ops (per-thread instruction, parallel issue across
// all blocks/threads); ~5 planes per block spread over 1184 blocks.
// ---------------------------------------------------------------------------
__global__ void __launch_bounds__(256) zero_kernel(float* __restrict__ y) {
    const int n = g_ndrop;
    const int t = threadIdx.x;
    __shared__ alignas(128) float zbuf[HW];     // 16 KB of zeros

    float4* zb = reinterpret_cast<float4*>(zbuf);
#pragma unroll
    for (int j = 0; j < 4; ++j)
        zb[t + 256 * j] = make_float4(0.0f, 0.0f, 0.0f, 0.0f);
    __syncthreads();
    asm volatile("fence.proxy.async.shared::cta;" ::: "memory");

    const unsigned int saddr =
        (unsigned int)__cvta_generic_to_shared(zbuf);
    const unsigned int nbytes = HW * 4;

    // uniform distribution: thread t of block b owns planes b + ZGRID*t + ...
    for (int i = blockIdx.x + ZGRID * t; i < n; i += ZGRID * 256) {
        float* gdst = y + (size_t)g_droplist[i] * HW;
        asm volatile(
            "cp.async.bulk.global.shared::cta.bulk_group [%0], [%1], %2;"
            :: "l"(gdst), "r"(saddr), "r"(nbytes) : "memory");
    }

    // per-thread group commit/wait (threads with no issues wait trivially)
    asm volatile("cp.async.bulk.commit_group;" ::: "memory");
    asm volatile("cp.async.bulk.wait_group 0;" ::: "memory");
    __syncthreads();
}

// ---------------------------------------------------------------------------
extern "C" void kernel_launch(void* const* d_in, const int* in_sizes, int n_in,
                              void* d_out, int out_size) {
    const float* x       = (const float*)d_in[0];
    const float* base_cr = (const float*)d_in[1];
    const float* embed   = (const float*)d_in[2];
    const float* snr_w1  = (const float*)d_in[3];
    const float* snr_b1  = (const float*)d_in[4];
    const float* snr_w2  = (const float*)d_in[5];
    const float* snr_b2  = (const float*)d_in[6];
    const float* sem_w   = (const float*)d_in[7];
    const float* cond_w  = (const float*)d_in[8];
    const float* out_w   = (const float*)d_in[9];
    const float* r_w1    = (const float*)d_in[10];
    const float* r_b1    = (const float*)d_in[11];
    const float* r_w2    = (const float*)d_in[12];
    const float* r_b2    = (const float*)d_in[13];
    const float* r_w3    = (const float*)d_in[14];
    const float* r_b3    = (const float*)d_in[15];
    const int*   ch_idx  = (const int*)d_in[16];
    const int*   snr_db  = (const int*)d_in[17];

    float* y      = (float*)d_out;
    float* out_cr = y + (size_t)NPLANES * HW;   // cr_values appended after y

    copy_reduce_kernel<<<NPLANES, 256>>>(x, y);
    select_kernel<<<NB, 256>>>(base_cr, embed, snr_w1, snr_b1, snr_w2, snr_b2,
                               sem_w, cond_w, out_w,
                               r_w1, r_b1, r_w2, r_b2, r_w3, r_b3,
                               ch_idx, snr_db, out_cr);
    zero_kernel<<<ZGRID, 256>>>(y);
}